// round 2
// baseline (speedup 1.0000x reference)
#include <cuda_runtime.h>

#define D 128
#define MAXN 50000
#define MAXE 800000

// Scratch (device globals — no runtime allocation allowed)
__device__ float g_agg[(size_t)MAXN * D];   // 25.6 MB aggregation buffer
__device__ float g_h[(size_t)MAXN * D];     // 25.6 MB hidden activations
__device__ float g_cnt[MAXN];
__device__ float g_inv[MAXN];
__device__ int   g_idx64;                   // 1 = edge_index is int64, 0 = int32

// ---------------------------------------------------------------------------
// Detect edge-index dtype: sample entries as int64; random int32 data
// reinterpreted as int64 yields values >= 2^32 with overwhelming probability.
// ---------------------------------------------------------------------------
__global__ void detect_kernel(const long long* __restrict__ e, int E, int N) {
    __shared__ int bad;
    if (threadIdx.x == 0) bad = 0;
    __syncthreads();
    int limit = 1024 < 2 * E ? 1024 : 2 * E;   // safe under either dtype
    // (int32 case: 2*E int32 = E int64-slots; limit<=1024 << E, in bounds)
    for (int i = threadIdx.x; i < limit; i += blockDim.x) {
        long long v = e[i];
        if (v < 0 || v >= (long long)N) bad = 1;
    }
    __syncthreads();
    if (threadIdx.x == 0) g_idx64 = bad ? 0 : 1;
}

// ---------------------------------------------------------------------------
// Zero the aggregation buffer (and optionally the degree counters)
// ---------------------------------------------------------------------------
__global__ void zero_kernel(int n4, int ncnt) {
    int i = blockIdx.x * blockDim.x + threadIdx.x;
    if (i < n4) reinterpret_cast<float4*>(g_agg)[i] = make_float4(0.f, 0.f, 0.f, 0.f);
    if (i < ncnt) g_cnt[i] = 0.f;
}

__global__ void inv_kernel(int n) {
    int i = blockIdx.x * blockDim.x + threadIdx.x;
    if (i < n) g_inv[i] = 1.0f / fmaxf(g_cnt[i], 1.0f);
}

// ---------------------------------------------------------------------------
// Edge scatter: one warp per edge. Each lane moves one float4 (128 floats/row).
// Vector reduction red.global.add.v4.f32 (sm_90+) => 32 RED.128 per edge.
// ---------------------------------------------------------------------------
__global__ void scatter_kernel(const float* __restrict__ Xin,
                               const void* __restrict__ eidx,
                               int E, int N, int do_count, int use_h) {
    int gid  = blockIdx.x * blockDim.x + threadIdx.x;
    int e    = gid >> 5;
    int lane = gid & 31;
    if (e >= E) return;

    const float* __restrict__ X = use_h ? g_h : Xin;

    long long s, d;
    if (g_idx64) {
        const long long* ei = (const long long*)eidx;
        s = ei[e];
        d = ei[e + E];
    } else {
        const int* ei = (const int*)eidx;
        s = ei[e];
        d = ei[e + E];
    }
    // Safety clamp: a bad index becomes a visible wrong answer, never an IMA.
    if (s < 0 || s >= N || d < 0 || d >= N) return;

    float4 v = reinterpret_cast<const float4*>(X + s * D)[lane];
    float4* a = reinterpret_cast<float4*>(g_agg + d * D) + lane;
    asm volatile("red.global.add.v4.f32 [%0], {%1, %2, %3, %4};"
                 :: "l"(a), "f"(v.x), "f"(v.y), "f"(v.z), "f"(v.w)
                 : "memory");
    if (do_count && lane == 0) atomicAdd(g_cnt + d, 1.0f);
}

// ---------------------------------------------------------------------------
// Fused SAGE layer GEMM:
//   out[i,:] = (g_agg[i,:] * g_inv[i]) @ Wl^T + bias + X[i,:] @ Wr^T  (+ReLU)
// Single 128x128 output tile per block, K=256 (k<128 -> agg/Wl, k>=128 -> X/Wr).
// 256 threads, 8x8 micro-tile each, split 4+4 over a 64-column half-split.
// ---------------------------------------------------------------------------
__global__ void __launch_bounds__(256, 2)
sage_gemm(const float* __restrict__ Xin,
          const float* __restrict__ Wl, const float* __restrict__ Wr,
          const float* __restrict__ bias,
          float* __restrict__ outp,
          int N, int relu, int x_is_h, int out_is_h) {
    __shared__ float As[32][128];
    __shared__ float Bs[32][128];

    const float* __restrict__ Xs = x_is_h ? g_h : Xin;
    float* __restrict__ out = out_is_h ? g_h : outp;

    int tid = threadIdx.x;
    int tx = tid & 15;
    int ty = tid >> 4;
    int row0 = blockIdx.x * 128;

    float acc[8][8];
#pragma unroll
    for (int i = 0; i < 8; i++)
#pragma unroll
        for (int j = 0; j < 8; j++) acc[i][j] = 0.f;

#pragma unroll
    for (int k0 = 0; k0 < 256; k0 += 32) {
        const bool isAgg = (k0 < 128);
        const int kb = isAgg ? k0 : (k0 - 128);
        const float* __restrict__ A = isAgg ? g_agg : Xs;
        const float* __restrict__ W = isAgg ? Wl : Wr;

        // Load 128x32 A tile and 128x32 W tile, transposed into k-major smem.
#pragma unroll
        for (int i = 0; i < 4; i++) {
            int f = i * 256 + tid;       // float4 index 0..1023
            int r = f >> 3;              // row 0..127
            int c = (f & 7) * 4;         // k-offset 0..28
            int row = row0 + r;
            float4 v = make_float4(0.f, 0.f, 0.f, 0.f);
            if (row < N) {
                v = *reinterpret_cast<const float4*>(A + (size_t)row * D + kb + c);
                if (isAgg) {
                    float sc = g_inv[row];
                    v.x *= sc; v.y *= sc; v.z *= sc; v.w *= sc;
                }
            }
            As[c + 0][r] = v.x; As[c + 1][r] = v.y;
            As[c + 2][r] = v.z; As[c + 3][r] = v.w;

            float4 w = *reinterpret_cast<const float4*>(W + (size_t)r * D + kb + c);
            Bs[c + 0][r] = w.x; Bs[c + 1][r] = w.y;
            Bs[c + 2][r] = w.z; Bs[c + 3][r] = w.w;
        }
        __syncthreads();

#pragma unroll
        for (int k = 0; k < 32; k++) {
            float a[8], b[8];
            *reinterpret_cast<float4*>(&a[0]) =
                *reinterpret_cast<const float4*>(&As[k][ty * 4]);
            *reinterpret_cast<float4*>(&a[4]) =
                *reinterpret_cast<const float4*>(&As[k][64 + ty * 4]);
            *reinterpret_cast<float4*>(&b[0]) =
                *reinterpret_cast<const float4*>(&Bs[k][tx * 4]);
            *reinterpret_cast<float4*>(&b[4]) =
                *reinterpret_cast<const float4*>(&Bs[k][64 + tx * 4]);
#pragma unroll
            for (int i = 0; i < 8; i++)
#pragma unroll
                for (int j = 0; j < 8; j++)
                    acc[i][j] += a[i] * b[j];
        }
        __syncthreads();
    }

    // Epilogue: bias (+ReLU), vectorized float4 stores.
    float4 b_lo = *reinterpret_cast<const float4*>(bias + tx * 4);
    float4 b_hi = *reinterpret_cast<const float4*>(bias + 64 + tx * 4);

#pragma unroll
    for (int i = 0; i < 8; i++) {
        int row = (i < 4) ? (row0 + ty * 4 + i) : (row0 + 64 + ty * 4 + (i - 4));
        if (row >= N) continue;
        float4 lo, hi;
        lo.x = acc[i][0] + b_lo.x; lo.y = acc[i][1] + b_lo.y;
        lo.z = acc[i][2] + b_lo.z; lo.w = acc[i][3] + b_lo.w;
        hi.x = acc[i][4] + b_hi.x; hi.y = acc[i][5] + b_hi.y;
        hi.z = acc[i][6] + b_hi.z; hi.w = acc[i][7] + b_hi.w;
        if (relu) {
            lo.x = fmaxf(lo.x, 0.f); lo.y = fmaxf(lo.y, 0.f);
            lo.z = fmaxf(lo.z, 0.f); lo.w = fmaxf(lo.w, 0.f);
            hi.x = fmaxf(hi.x, 0.f); hi.y = fmaxf(hi.y, 0.f);
            hi.z = fmaxf(hi.z, 0.f); hi.w = fmaxf(hi.w, 0.f);
        }
        *reinterpret_cast<float4*>(out + (size_t)row * D + tx * 4) = lo;
        *reinterpret_cast<float4*>(out + (size_t)row * D + 64 + tx * 4) = hi;
    }
}

// ---------------------------------------------------------------------------
extern "C" void kernel_launch(void* const* d_in, const int* in_sizes, int n_in,
                              void* d_out, int out_size) {
    const float*     x   = (const float*)d_in[0];
    const void*      ei  = d_in[1];
    const float*     Wl0 = (const float*)d_in[2];
    const float*     bl0 = (const float*)d_in[3];
    const float*     Wr0 = (const float*)d_in[4];
    const float*     Wl1 = (const float*)d_in[5];
    const float*     bl1 = (const float*)d_in[6];
    const float*     Wr1 = (const float*)d_in[7];
    float*           out = (float*)d_out;

    int N = in_sizes[0] / D;
    int E = in_sizes[1] / 2;

    int n4 = N * (D / 4);
    int zero_blocks    = (n4 + 255) / 256;
    int scatter_blocks = (E * 32 + 255) / 256;
    int inv_blocks     = (N + 255) / 256;
    int gemm_blocks    = (N + 127) / 128;

    detect_kernel<<<1, 256>>>((const long long*)ei, E, N);

    // Layer 0
    zero_kernel<<<zero_blocks, 256>>>(n4, N);
    scatter_kernel<<<scatter_blocks, 256>>>(x, ei, E, N, /*count=*/1, /*use_h=*/0);
    inv_kernel<<<inv_blocks, 256>>>(N);
    sage_gemm<<<gemm_blocks, 256>>>(x, Wl0, Wr0, bl0, out, N,
                                    /*relu=*/1, /*x_is_h=*/0, /*out_is_h=*/1);
    // Layer 1
    zero_kernel<<<zero_blocks, 256>>>(n4, 0);
    scatter_kernel<<<scatter_blocks, 256>>>(x, ei, E, N, /*count=*/0, /*use_h=*/1);
    sage_gemm<<<gemm_blocks, 256>>>(x, Wl1, Wr1, bl1, out, N,
                                    /*relu=*/0, /*x_is_h=*/1, /*out_is_h=*/0);
}

// round 4
// speedup vs baseline: 1.5190x; 1.5190x over previous
#include <cuda_runtime.h>
#include <cuda_bf16.h>
#include <cstdint>

#define D 128
#define MAXN 50000

// Scratch (device globals — no runtime allocation allowed)
__device__ float g_agg[(size_t)MAXN * D];   // 25.6 MB aggregation buffer
__device__ float g_h[(size_t)MAXN * D];     // 25.6 MB hidden activations
__device__ float g_cnt[MAXN];
__device__ float g_inv[MAXN];
__device__ int   g_idx64;                   // 1 = edge_index is int64, 0 = int32

// ---------------------------------------------------------------------------
__device__ __forceinline__ uint32_t smem_u32(const void* p) {
    uint32_t a;
    asm("{ .reg .u64 t; cvta.to.shared.u64 t, %1; cvt.u32.u64 %0, t; }"
        : "=r"(a) : "l"(p));
    return a;
}
__device__ __forceinline__ void ldsm_x4(uint32_t& r0, uint32_t& r1,
                                        uint32_t& r2, uint32_t& r3, uint32_t addr) {
    asm volatile("ldmatrix.sync.aligned.m8n8.x4.shared.b16 {%0,%1,%2,%3}, [%4];"
                 : "=r"(r0), "=r"(r1), "=r"(r2), "=r"(r3) : "r"(addr));
}
__device__ __forceinline__ void mma_bf16(float* c, const uint32_t* a, const uint32_t* b) {
    asm volatile(
        "mma.sync.aligned.m16n8k16.row.col.f32.bf16.bf16.f32 "
        "{%0,%1,%2,%3}, {%4,%5,%6,%7}, {%8,%9}, {%0,%1,%2,%3};"
        : "+f"(c[0]), "+f"(c[1]), "+f"(c[2]), "+f"(c[3])
        : "r"(a[0]), "r"(a[1]), "r"(a[2]), "r"(a[3]), "r"(b[0]), "r"(b[1]));
}

// ---------------------------------------------------------------------------
// Detect edge-index dtype (int64 vs int32 silently produced by JAX)
// ---------------------------------------------------------------------------
__global__ void detect_kernel(const long long* __restrict__ e, int E, int N) {
    __shared__ int bad;
    if (threadIdx.x == 0) bad = 0;
    __syncthreads();
    int limit = 1024 < 2 * E ? 1024 : 2 * E;
    for (int i = threadIdx.x; i < limit; i += blockDim.x) {
        long long v = e[i];
        if (v < 0 || v >= (long long)N) bad = 1;
    }
    __syncthreads();
    if (threadIdx.x == 0) g_idx64 = bad ? 0 : 1;
}

__global__ void zero_kernel(int n4, int ncnt) {
    int i = blockIdx.x * blockDim.x + threadIdx.x;
    if (i < n4) reinterpret_cast<float4*>(g_agg)[i] = make_float4(0.f, 0.f, 0.f, 0.f);
    if (i < ncnt) g_cnt[i] = 0.f;
}

__global__ void inv_kernel(int n) {
    int i = blockIdx.x * blockDim.x + threadIdx.x;
    if (i < n) g_inv[i] = 1.0f / fmaxf(g_cnt[i], 1.0f);
}

// ---------------------------------------------------------------------------
// Edge scatter: one warp per edge, red.global.add.v4.f32
// ---------------------------------------------------------------------------
__global__ void scatter_kernel(const float* __restrict__ Xin,
                               const void* __restrict__ eidx,
                               int E, int N, int do_count, int use_h) {
    int gid  = blockIdx.x * blockDim.x + threadIdx.x;
    int e    = gid >> 5;
    int lane = gid & 31;
    if (e >= E) return;

    const float* __restrict__ X = use_h ? g_h : Xin;

    long long s, d;
    if (g_idx64) {
        const long long* ei = (const long long*)eidx;
        s = ei[e];
        d = ei[e + E];
    } else {
        const int* ei = (const int*)eidx;
        s = ei[e];
        d = ei[e + E];
    }
    if (s < 0 || s >= N || d < 0 || d >= N) return;

    float4 v = reinterpret_cast<const float4*>(X + s * D)[lane];
    float4* a = reinterpret_cast<float4*>(g_agg + d * D) + lane;
    asm volatile("red.global.add.v4.f32 [%0], {%1, %2, %3, %4};"
                 :: "l"(a), "f"(v.x), "f"(v.y), "f"(v.z), "f"(v.w)
                 : "memory");
    if (do_count && lane == 0) atomicAdd(g_cnt + d, 1.0f);
}

// ---------------------------------------------------------------------------
// mma.sync bf16-split fused SAGE layer GEMM.
//   out[i,:] = (g_agg[i,:]*g_inv[i]) @ Wl^T + bias + X[i,:] @ Wr^T  (+ReLU)
// 128x128 tile per CTA, K=256 in 4 chunks of 64. Each fp32 operand split
// a = a_hi + a_lo (bf16); D += Ahi*Bhi + Ahi*Blo + Alo*Bhi (err ~2^-18).
// 8 warps = 4(M) x 2(N); warp tile 32x64; m16n8k16 HMMA.
// ---------------------------------------------------------------------------
#define ROWB 144                 // smem row stride bytes (64 bf16 + 8 pad)
#define TILE_BYTES (128 * ROWB)  // 18432
#define SA_HI 0
#define SA_LO (SA_HI + TILE_BYTES)
#define SB_HI (SA_LO + TILE_BYTES)
#define SB_LO (SB_HI + TILE_BYTES)
#define SMEM_TOTAL (4 * TILE_BYTES)   // 73728

__device__ __forceinline__ void split_store(char* smem, int hi_off, int lo_off,
                                            int row, int col, float4 v) {
    __nv_bfloat16 h0 = __float2bfloat16(v.x);
    __nv_bfloat16 h1 = __float2bfloat16(v.y);
    __nv_bfloat16 h2 = __float2bfloat16(v.z);
    __nv_bfloat16 h3 = __float2bfloat16(v.w);
    __nv_bfloat16 l0 = __float2bfloat16(v.x - __bfloat162float(h0));
    __nv_bfloat16 l1 = __float2bfloat16(v.y - __bfloat162float(h1));
    __nv_bfloat16 l2 = __float2bfloat16(v.z - __bfloat162float(h2));
    __nv_bfloat16 l3 = __float2bfloat16(v.w - __bfloat162float(h3));
    uint2 hi, lo;
    hi.x = (uint32_t)__bfloat16_as_ushort(h0) | ((uint32_t)__bfloat16_as_ushort(h1) << 16);
    hi.y = (uint32_t)__bfloat16_as_ushort(h2) | ((uint32_t)__bfloat16_as_ushort(h3) << 16);
    lo.x = (uint32_t)__bfloat16_as_ushort(l0) | ((uint32_t)__bfloat16_as_ushort(l1) << 16);
    lo.y = (uint32_t)__bfloat16_as_ushort(l2) | ((uint32_t)__bfloat16_as_ushort(l3) << 16);
    int b = row * ROWB + col * 2;
    *reinterpret_cast<uint2*>(smem + hi_off + b) = hi;
    *reinterpret_cast<uint2*>(smem + lo_off + b) = lo;
}

__global__ void __launch_bounds__(256, 2)
sage_gemm_tc(const float* __restrict__ Xin,
             const float* __restrict__ Wl, const float* __restrict__ Wr,
             const float* __restrict__ bias,
             float* __restrict__ outp,
             int N, int relu, int x_is_h, int out_is_h) {
    extern __shared__ __align__(128) char smem[];
    uint32_t sb = smem_u32(smem);

    int tid = threadIdx.x, wid = tid >> 5, lane = tid & 31;
    int warpM = wid & 3, warpN = wid >> 2;
    int row0 = blockIdx.x * 128;

    const float* __restrict__ Xs = x_is_h ? g_h : Xin;
    float* __restrict__ out = out_is_h ? g_h : outp;

    // Per-thread ldmatrix byte offsets (within a tile)
    uint32_t aoff[2], boff[4];
#pragma unroll
    for (int mi = 0; mi < 2; mi++)
        aoff[mi] = (uint32_t)((warpM * 32 + mi * 16 + (lane & 15)) * ROWB + (lane >> 4) * 16);
#pragma unroll
    for (int np = 0; np < 4; np++)
        boff[np] = (uint32_t)((warpN * 64 + np * 16 + (lane & 7) + ((lane & 16) ? 8 : 0)) * ROWB
                              + ((lane >> 3) & 1) * 16);

    float acc[2][8][4];
#pragma unroll
    for (int mi = 0; mi < 2; mi++)
#pragma unroll
        for (int ni = 0; ni < 8; ni++)
#pragma unroll
            for (int j = 0; j < 4; j++) acc[mi][ni][j] = 0.f;

    for (int c = 0; c < 4; c++) {
        const bool isAgg = (c < 2);
        const float* __restrict__ A = isAgg ? g_agg : Xs;
        const float* __restrict__ W = isAgg ? Wl : Wr;
        const int kb = (c & 1) * 64;

        if (c > 0) __syncthreads();   // previous chunk's MMAs done reading smem

        // Load 128x64 fp32 tiles, split to hi/lo bf16 smem
#pragma unroll
        for (int i = 0; i < 8; i++) {
            int f = i * 256 + tid;    // float4 index 0..2047
            int r = f >> 4;           // row 0..127
            int col = (f & 15) * 4;   // 0..60
            int row = row0 + r;
            float4 v = make_float4(0.f, 0.f, 0.f, 0.f);
            if (row < N) {
                v = *reinterpret_cast<const float4*>(A + (size_t)row * D + kb + col);
                if (isAgg) {
                    float sc = g_inv[row];
                    v.x *= sc; v.y *= sc; v.z *= sc; v.w *= sc;
                }
            }
            split_store(smem, SA_HI, SA_LO, r, col, v);

            float4 w = *reinterpret_cast<const float4*>(W + (size_t)r * D + kb + col);
            split_store(smem, SB_HI, SB_LO, r, col, w);
        }
        __syncthreads();

        // 3 split passes: (Ahi,Bhi), (Ahi,Blo), (Alo,Bhi)
#pragma unroll
        for (int p = 0; p < 3; p++) {
            uint32_t abase = sb + ((p == 2) ? SA_LO : SA_HI);
            uint32_t bbase = sb + ((p == 1) ? SB_LO : SB_HI);
#pragma unroll
            for (int ks = 0; ks < 4; ks++) {
                uint32_t kbyte = (uint32_t)(ks * 32);
                uint32_t a[2][4], b[8][2];
#pragma unroll
                for (int mi = 0; mi < 2; mi++)
                    ldsm_x4(a[mi][0], a[mi][1], a[mi][2], a[mi][3],
                            abase + aoff[mi] + kbyte);
#pragma unroll
                for (int np = 0; np < 4; np++)
                    ldsm_x4(b[2 * np][0], b[2 * np][1], b[2 * np + 1][0], b[2 * np + 1][1],
                            bbase + boff[np] + kbyte);
#pragma unroll
                for (int mi = 0; mi < 2; mi++)
#pragma unroll
                    for (int ni = 0; ni < 8; ni++)
                        mma_bf16(acc[mi][ni], a[mi], b[ni]);
            }
        }
    }

    // Epilogue: bias (+ReLU), float2 stores.
    int g = lane >> 2, t = lane & 3;
#pragma unroll
    for (int mi = 0; mi < 2; mi++) {
        int r1 = row0 + warpM * 32 + mi * 16 + g;
        int r2 = r1 + 8;
#pragma unroll
        for (int ni = 0; ni < 8; ni++) {
            int col = warpN * 64 + ni * 8 + t * 2;
            float2 bs = *reinterpret_cast<const float2*>(bias + col);
            float2 o1, o2;
            o1.x = acc[mi][ni][0] + bs.x; o1.y = acc[mi][ni][1] + bs.y;
            o2.x = acc[mi][ni][2] + bs.x; o2.y = acc[mi][ni][3] + bs.y;
            if (relu) {
                o1.x = fmaxf(o1.x, 0.f); o1.y = fmaxf(o1.y, 0.f);
                o2.x = fmaxf(o2.x, 0.f); o2.y = fmaxf(o2.y, 0.f);
            }
            if (r1 < N) *reinterpret_cast<float2*>(out + (size_t)r1 * D + col) = o1;
            if (r2 < N) *reinterpret_cast<float2*>(out + (size_t)r2 * D + col) = o2;
        }
    }
}

// ---------------------------------------------------------------------------
extern "C" void kernel_launch(void* const* d_in, const int* in_sizes, int n_in,
                              void* d_out, int out_size) {
    const float* x   = (const float*)d_in[0];
    const void*  ei  = d_in[1];
    const float* Wl0 = (const float*)d_in[2];
    const float* bl0 = (const float*)d_in[3];
    const float* Wr0 = (const float*)d_in[4];
    const float* Wl1 = (const float*)d_in[5];
    const float* bl1 = (const float*)d_in[6];
    const float* Wr1 = (const float*)d_in[7];
    float*       out = (float*)d_out;

    int N = in_sizes[0] / D;
    int E = in_sizes[1] / 2;

    int n4 = N * (D / 4);
    int zero_blocks    = (n4 + 255) / 256;
    int scatter_blocks = (E * 32 + 255) / 256;
    int inv_blocks     = (N + 255) / 256;
    int gemm_blocks    = (N + 127) / 128;

    // Idempotent, non-stream call: safe under graph capture on every invocation.
    cudaFuncSetAttribute(sage_gemm_tc,
                         cudaFuncAttributeMaxDynamicSharedMemorySize, SMEM_TOTAL);

    detect_kernel<<<1, 256>>>((const long long*)ei, E, N);

    // Layer 0
    zero_kernel<<<zero_blocks, 256>>>(n4, N);
    scatter_kernel<<<scatter_blocks, 256>>>(x, ei, E, N, /*count=*/1, /*use_h=*/0);
    inv_kernel<<<inv_blocks, 256>>>(N);
    sage_gemm_tc<<<gemm_blocks, 256, SMEM_TOTAL>>>(x, Wl0, Wr0, bl0, out, N,
                                                   /*relu=*/1, /*x_is_h=*/0, /*out_is_h=*/1);
    // Layer 1
    zero_kernel<<<zero_blocks, 256>>>(n4, 0);
    scatter_kernel<<<scatter_blocks, 256>>>(x, ei, E, N, /*count=*/0, /*use_h=*/1);
    sage_gemm_tc<<<gemm_blocks, 256, SMEM_TOTAL>>>(x, Wl1, Wr1, bl1, out, N,
                                                   /*relu=*/0, /*x_is_h=*/1, /*out_is_h=*/0);
}

// round 5
// speedup vs baseline: 2.3511x; 1.5479x over previous
#include <cuda_runtime.h>
#include <cuda_bf16.h>
#include <cstdint>

#define D 128
#define MAXN 50000
#define MAXE 800000
#define SCAN_BLK 512
#define SCAN_GRID ((MAXN + SCAN_BLK - 1) / SCAN_BLK)   // 98

// Scratch (device globals — no runtime allocation allowed)
__device__ float g_agg[(size_t)MAXN * D];   // 25.6 MB aggregation buffer
__device__ float g_h[(size_t)MAXN * D];     // 25.6 MB hidden activations
__device__ int   g_deg[MAXN];               // degree -> exclusive scan (in place)
__device__ int   g_part[SCAN_GRID];         // per-block partial sums
__device__ int   g_rowptr[MAXN + 1];
__device__ int   g_cursor[MAXN];
__device__ int   g_perm[MAXE];              // src ids grouped by dst
__device__ int   g_idx64;                   // 1 = edge_index is int64, 0 = int32

// ---------------------------------------------------------------------------
__device__ __forceinline__ uint32_t smem_u32(const void* p) {
    uint32_t a;
    asm("{ .reg .u64 t; cvta.to.shared.u64 t, %1; cvt.u32.u64 %0, t; }"
        : "=r"(a) : "l"(p));
    return a;
}
__device__ __forceinline__ void ldsm_x4(uint32_t& r0, uint32_t& r1,
                                        uint32_t& r2, uint32_t& r3, uint32_t addr) {
    asm volatile("ldmatrix.sync.aligned.m8n8.x4.shared.b16 {%0,%1,%2,%3}, [%4];"
                 : "=r"(r0), "=r"(r1), "=r"(r2), "=r"(r3) : "r"(addr));
}
__device__ __forceinline__ void mma_bf16(float* c, const uint32_t* a, const uint32_t* b) {
    asm volatile(
        "mma.sync.aligned.m16n8k16.row.col.f32.bf16.bf16.f32 "
        "{%0,%1,%2,%3}, {%4,%5,%6,%7}, {%8,%9}, {%0,%1,%2,%3};"
        : "+f"(c[0]), "+f"(c[1]), "+f"(c[2]), "+f"(c[3])
        : "r"(a[0]), "r"(a[1]), "r"(a[2]), "r"(a[3]), "r"(b[0]), "r"(b[1]));
}

// Read edge endpoint under either index dtype, clamped for safety.
__device__ __forceinline__ int edge_at(const void* eidx, int i, int N) {
    long long v;
    if (g_idx64) v = ((const long long*)eidx)[i];
    else         v = ((const int*)eidx)[i];
    if (v < 0) v = 0;
    if (v >= N) v = N - 1;
    return (int)v;
}

// ---------------------------------------------------------------------------
// Detect edge-index dtype (int64 vs int32 silently produced by JAX)
// ---------------------------------------------------------------------------
__global__ void detect_kernel(const long long* __restrict__ e, int E, int N) {
    __shared__ int bad;
    if (threadIdx.x == 0) bad = 0;
    __syncthreads();
    int limit = 1024 < 2 * E ? 1024 : 2 * E;
    for (int i = threadIdx.x; i < limit; i += blockDim.x) {
        long long v = e[i];
        if (v < 0 || v >= (long long)N) bad = 1;
    }
    __syncthreads();
    if (threadIdx.x == 0) g_idx64 = bad ? 0 : 1;
}

// ---------------------------------------------------------------------------
// CSR build: degree count -> exclusive scan -> fill permutation
// ---------------------------------------------------------------------------
__global__ void zero_deg_kernel(int N) {
    int i = blockIdx.x * blockDim.x + threadIdx.x;
    if (i < N) g_deg[i] = 0;
}

__global__ void count_kernel(const void* __restrict__ eidx, int E, int N) {
    int e = blockIdx.x * blockDim.x + threadIdx.x;
    if (e >= E) return;
    int d = edge_at(eidx, e + E, N);
    atomicAdd(&g_deg[d], 1);
}

__global__ void scan1_kernel(int N) {
    __shared__ int sh[SCAN_BLK];
    int t = threadIdx.x;
    int i = blockIdx.x * SCAN_BLK + t;
    int v = (i < N) ? g_deg[i] : 0;
    sh[t] = v;
    __syncthreads();
#pragma unroll
    for (int ofs = 1; ofs < SCAN_BLK; ofs <<= 1) {
        int add = (t >= ofs) ? sh[t - ofs] : 0;
        __syncthreads();
        sh[t] += add;
        __syncthreads();
    }
    if (i < N) g_deg[i] = sh[t] - v;          // exclusive, in place
    if (t == SCAN_BLK - 1) g_part[blockIdx.x] = sh[t];
}

__global__ void scan2_kernel(int nb) {
    __shared__ int sh[128];
    int t = threadIdx.x;
    int v = (t < nb) ? g_part[t] : 0;
    sh[t] = v;
    __syncthreads();
#pragma unroll
    for (int ofs = 1; ofs < 128; ofs <<= 1) {
        int add = (t >= ofs) ? sh[t - ofs] : 0;
        __syncthreads();
        sh[t] += add;
        __syncthreads();
    }
    if (t < nb) g_part[t] = sh[t] - v;        // exclusive block offsets
}

__global__ void scan3_kernel(int N, int E) {
    int i = blockIdx.x * SCAN_BLK + threadIdx.x;
    if (i < N) {
        int r = g_deg[i] + g_part[i >> 9];    // SCAN_BLK == 512
        g_rowptr[i] = r;
        g_cursor[i] = r;
    }
    if (i == N) g_rowptr[N] = E;
}

__global__ void fill_kernel(const void* __restrict__ eidx, int E, int N) {
    int e = blockIdx.x * blockDim.x + threadIdx.x;
    if (e >= E) return;
    int s = edge_at(eidx, e, N);
    int d = edge_at(eidx, e + E, N);
    int pos = atomicAdd(&g_cursor[d], 1);
    g_perm[pos] = s;
}

// ---------------------------------------------------------------------------
// Gather aggregation: one warp per dst node. No atomics, single write of the
// mean row. Neighbor ids broadcast via shfl; each lane owns one float4 of the
// 128-float row.
// ---------------------------------------------------------------------------
__global__ void __launch_bounds__(256)
agg_kernel(const float* __restrict__ Xin, int N, int use_h) {
    int gw = (blockIdx.x * blockDim.x + threadIdx.x) >> 5;
    int lane = threadIdx.x & 31;
    if (gw >= N) return;

    const float* __restrict__ X = use_h ? g_h : Xin;
    int beg = g_rowptr[gw];
    int end = g_rowptr[gw + 1];

    float4 acc = make_float4(0.f, 0.f, 0.f, 0.f);
    for (int base = beg; base < end; base += 32) {
        int idx = base + lane;
        int sv = (idx < end) ? g_perm[idx] : 0;
        int m = min(32, end - base);
        for (int j = 0; j < m; j++) {
            int s = __shfl_sync(0xffffffffu, sv, j);
            float4 v = reinterpret_cast<const float4*>(X + (size_t)s * D)[lane];
            acc.x += v.x; acc.y += v.y; acc.z += v.z; acc.w += v.w;
        }
    }
    float inv = (end > beg) ? 1.0f / (float)(end - beg) : 0.f;
    acc.x *= inv; acc.y *= inv; acc.z *= inv; acc.w *= inv;
    reinterpret_cast<float4*>(g_agg + (size_t)gw * D)[lane] = acc;
}

// ---------------------------------------------------------------------------
// mma.sync bf16-split fused SAGE layer GEMM.
//   out[i,:] = g_agg[i,:] @ Wl^T + bias + X[i,:] @ Wr^T  (+ReLU)
// (g_agg already holds the neighbor MEAN.)
// ---------------------------------------------------------------------------
#define ROWB 144                 // smem row stride bytes (64 bf16 + 8 pad)
#define TILE_BYTES (128 * ROWB)  // 18432
#define SA_HI 0
#define SA_LO (SA_HI + TILE_BYTES)
#define SB_HI (SA_LO + TILE_BYTES)
#define SB_LO (SB_HI + TILE_BYTES)
#define SMEM_TOTAL (4 * TILE_BYTES)   // 73728

__device__ __forceinline__ void split_store(char* smem, int hi_off, int lo_off,
                                            int row, int col, float4 v) {
    __nv_bfloat16 h0 = __float2bfloat16(v.x);
    __nv_bfloat16 h1 = __float2bfloat16(v.y);
    __nv_bfloat16 h2 = __float2bfloat16(v.z);
    __nv_bfloat16 h3 = __float2bfloat16(v.w);
    __nv_bfloat16 l0 = __float2bfloat16(v.x - __bfloat162float(h0));
    __nv_bfloat16 l1 = __float2bfloat16(v.y - __bfloat162float(h1));
    __nv_bfloat16 l2 = __float2bfloat16(v.z - __bfloat162float(h2));
    __nv_bfloat16 l3 = __float2bfloat16(v.w - __bfloat162float(h3));
    uint2 hi, lo;
    hi.x = (uint32_t)__bfloat16_as_ushort(h0) | ((uint32_t)__bfloat16_as_ushort(h1) << 16);
    hi.y = (uint32_t)__bfloat16_as_ushort(h2) | ((uint32_t)__bfloat16_as_ushort(h3) << 16);
    lo.x = (uint32_t)__bfloat16_as_ushort(l0) | ((uint32_t)__bfloat16_as_ushort(l1) << 16);
    lo.y = (uint32_t)__bfloat16_as_ushort(l2) | ((uint32_t)__bfloat16_as_ushort(l3) << 16);
    int b = row * ROWB + col * 2;
    *reinterpret_cast<uint2*>(smem + hi_off + b) = hi;
    *reinterpret_cast<uint2*>(smem + lo_off + b) = lo;
}

__global__ void __launch_bounds__(256, 2)
sage_gemm_tc(const float* __restrict__ Xin,
             const float* __restrict__ Wl, const float* __restrict__ Wr,
             const float* __restrict__ bias,
             float* __restrict__ outp,
             int N, int relu, int x_is_h, int out_is_h) {
    extern __shared__ __align__(128) char smem[];
    uint32_t sb = smem_u32(smem);

    int tid = threadIdx.x, wid = tid >> 5, lane = tid & 31;
    int warpM = wid & 3, warpN = wid >> 2;
    int row0 = blockIdx.x * 128;

    const float* __restrict__ Xs = x_is_h ? g_h : Xin;
    float* __restrict__ out = out_is_h ? g_h : outp;

    uint32_t aoff[2], boff[4];
#pragma unroll
    for (int mi = 0; mi < 2; mi++)
        aoff[mi] = (uint32_t)((warpM * 32 + mi * 16 + (lane & 15)) * ROWB + (lane >> 4) * 16);
#pragma unroll
    for (int np = 0; np < 4; np++)
        boff[np] = (uint32_t)((warpN * 64 + np * 16 + (lane & 7) + ((lane & 16) ? 8 : 0)) * ROWB
                              + ((lane >> 3) & 1) * 16);

    float acc[2][8][4];
#pragma unroll
    for (int mi = 0; mi < 2; mi++)
#pragma unroll
        for (int ni = 0; ni < 8; ni++)
#pragma unroll
            for (int j = 0; j < 4; j++) acc[mi][ni][j] = 0.f;

    for (int c = 0; c < 4; c++) {
        const bool isAgg = (c < 2);
        const float* __restrict__ A = isAgg ? g_agg : Xs;
        const float* __restrict__ W = isAgg ? Wl : Wr;
        const int kb = (c & 1) * 64;

        if (c > 0) __syncthreads();

#pragma unroll
        for (int i = 0; i < 8; i++) {
            int f = i * 256 + tid;
            int r = f >> 4;
            int col = (f & 15) * 4;
            int row = row0 + r;
            float4 v = make_float4(0.f, 0.f, 0.f, 0.f);
            if (row < N)
                v = *reinterpret_cast<const float4*>(A + (size_t)row * D + kb + col);
            split_store(smem, SA_HI, SA_LO, r, col, v);

            float4 w = *reinterpret_cast<const float4*>(W + (size_t)r * D + kb + col);
            split_store(smem, SB_HI, SB_LO, r, col, w);
        }
        __syncthreads();

#pragma unroll
        for (int p = 0; p < 3; p++) {
            uint32_t abase = sb + ((p == 2) ? SA_LO : SA_HI);
            uint32_t bbase = sb + ((p == 1) ? SB_LO : SB_HI);
#pragma unroll
            for (int ks = 0; ks < 4; ks++) {
                uint32_t kbyte = (uint32_t)(ks * 32);
                uint32_t a[2][4], b[8][2];
#pragma unroll
                for (int mi = 0; mi < 2; mi++)
                    ldsm_x4(a[mi][0], a[mi][1], a[mi][2], a[mi][3],
                            abase + aoff[mi] + kbyte);
#pragma unroll
                for (int np = 0; np < 4; np++)
                    ldsm_x4(b[2 * np][0], b[2 * np][1], b[2 * np + 1][0], b[2 * np + 1][1],
                            bbase + boff[np] + kbyte);
#pragma unroll
                for (int mi = 0; mi < 2; mi++)
#pragma unroll
                    for (int ni = 0; ni < 8; ni++)
                        mma_bf16(acc[mi][ni], a[mi], b[ni]);
            }
        }
    }

    int g = lane >> 2, t = lane & 3;
#pragma unroll
    for (int mi = 0; mi < 2; mi++) {
        int r1 = row0 + warpM * 32 + mi * 16 + g;
        int r2 = r1 + 8;
#pragma unroll
        for (int ni = 0; ni < 8; ni++) {
            int col = warpN * 64 + ni * 8 + t * 2;
            float2 bs = *reinterpret_cast<const float2*>(bias + col);
            float2 o1, o2;
            o1.x = acc[mi][ni][0] + bs.x; o1.y = acc[mi][ni][1] + bs.y;
            o2.x = acc[mi][ni][2] + bs.x; o2.y = acc[mi][ni][3] + bs.y;
            if (relu) {
                o1.x = fmaxf(o1.x, 0.f); o1.y = fmaxf(o1.y, 0.f);
                o2.x = fmaxf(o2.x, 0.f); o2.y = fmaxf(o2.y, 0.f);
            }
            if (r1 < N) *reinterpret_cast<float2*>(out + (size_t)r1 * D + col) = o1;
            if (r2 < N) *reinterpret_cast<float2*>(out + (size_t)r2 * D + col) = o2;
        }
    }
}

// ---------------------------------------------------------------------------
extern "C" void kernel_launch(void* const* d_in, const int* in_sizes, int n_in,
                              void* d_out, int out_size) {
    const float* x   = (const float*)d_in[0];
    const void*  ei  = d_in[1];
    const float* Wl0 = (const float*)d_in[2];
    const float* bl0 = (const float*)d_in[3];
    const float* Wr0 = (const float*)d_in[4];
    const float* Wl1 = (const float*)d_in[5];
    const float* bl1 = (const float*)d_in[6];
    const float* Wr1 = (const float*)d_in[7];
    float*       out = (float*)d_out;

    int N = in_sizes[0] / D;
    int E = in_sizes[1] / 2;

    int edge_blocks = (E + 255) / 256;
    int node_blocks = (N + 255) / 256;
    int scan_grid   = (N + SCAN_BLK - 1) / SCAN_BLK;
    int scan3_grid  = (N + 1 + SCAN_BLK - 1) / SCAN_BLK;
    int agg_blocks  = (N * 32 + 255) / 256;
    int gemm_blocks = (N + 127) / 128;

    cudaFuncSetAttribute(sage_gemm_tc,
                         cudaFuncAttributeMaxDynamicSharedMemorySize, SMEM_TOTAL);

    detect_kernel<<<1, 256>>>((const long long*)ei, E, N);

    // CSR build (per launch; deterministic work)
    zero_deg_kernel<<<node_blocks, 256>>>(N);
    count_kernel<<<edge_blocks, 256>>>(ei, E, N);
    scan1_kernel<<<scan_grid, SCAN_BLK>>>(N);
    scan2_kernel<<<1, 128>>>(scan_grid);
    scan3_kernel<<<scan3_grid, SCAN_BLK>>>(N, E);
    fill_kernel<<<edge_blocks, 256>>>(ei, E, N);

    // Layer 0
    agg_kernel<<<agg_blocks, 256>>>(x, N, /*use_h=*/0);
    sage_gemm_tc<<<gemm_blocks, 256, SMEM_TOTAL>>>(x, Wl0, Wr0, bl0, out, N,
                                                   /*relu=*/1, /*x_is_h=*/0, /*out_is_h=*/1);
    // Layer 1
    agg_kernel<<<agg_blocks, 256>>>(x, N, /*use_h=*/1);
    sage_gemm_tc<<<gemm_blocks, 256, SMEM_TOTAL>>>(x, Wl1, Wr1, bl1, out, N,
                                                   /*relu=*/0, /*x_is_h=*/1, /*out_is_h=*/0);
}

// round 6
// speedup vs baseline: 2.3564x; 1.0022x over previous
#include <cuda_runtime.h>
#include <cuda_bf16.h>
#include <cuda_fp16.h>
#include <cstdint>

#define D 128
#define MAXN 50000
#define MAXE 800000
#define SCAN_BLK 512
#define SCAN_GRID ((MAXN + SCAN_BLK - 1) / SCAN_BLK)   // 98

// Scratch (device globals — no runtime allocation allowed)
__device__ float  g_agg[(size_t)MAXN * D];   // 25.6 MB aggregation buffer (fp32)
__device__ float  g_h[(size_t)MAXN * D];     // 25.6 MB hidden activations (fp32)
__device__ __half g_xh[(size_t)MAXN * D];    // 12.8 MB fp16 copy of x
__device__ __half g_hh[(size_t)MAXN * D];    // 12.8 MB fp16 copy of h
__device__ int    g_deg[MAXN];               // degree -> exclusive scan (in place)
__device__ int    g_part[SCAN_GRID];         // per-block partial sums
__device__ int    g_rowptr[MAXN + 1];
__device__ int    g_cursor[MAXN];
__device__ int    g_perm[MAXE];              // src ids grouped by dst
__device__ int    g_idx64;                   // 1 = edge_index is int64, 0 = int32

// ---------------------------------------------------------------------------
__device__ __forceinline__ uint32_t smem_u32(const void* p) {
    uint32_t a;
    asm("{ .reg .u64 t; cvta.to.shared.u64 t, %1; cvt.u32.u64 %0, t; }"
        : "=r"(a) : "l"(p));
    return a;
}
__device__ __forceinline__ void ldsm_x4(uint32_t& r0, uint32_t& r1,
                                        uint32_t& r2, uint32_t& r3, uint32_t addr) {
    asm volatile("ldmatrix.sync.aligned.m8n8.x4.shared.b16 {%0,%1,%2,%3}, [%4];"
                 : "=r"(r0), "=r"(r1), "=r"(r2), "=r"(r3) : "r"(addr));
}
__device__ __forceinline__ void mma_bf16(float* c, const uint32_t* a, const uint32_t* b) {
    asm volatile(
        "mma.sync.aligned.m16n8k16.row.col.f32.bf16.bf16.f32 "
        "{%0,%1,%2,%3}, {%4,%5,%6,%7}, {%8,%9}, {%0,%1,%2,%3};"
        : "+f"(c[0]), "+f"(c[1]), "+f"(c[2]), "+f"(c[3])
        : "r"(a[0]), "r"(a[1]), "r"(a[2]), "r"(a[3]), "r"(b[0]), "r"(b[1]));
}

// Read edge endpoint under either index dtype, clamped for safety.
__device__ __forceinline__ int edge_at(const void* eidx, int i, int N) {
    long long v;
    if (g_idx64) v = ((const long long*)eidx)[i];
    else         v = ((const int*)eidx)[i];
    if (v < 0) v = 0;
    if (v >= N) v = N - 1;
    return (int)v;
}

// ---------------------------------------------------------------------------
// Detect edge-index dtype + zero the degree array (merged)
// ---------------------------------------------------------------------------
__global__ void detect_zero_kernel(const long long* __restrict__ e, int E, int N) {
    int i = blockIdx.x * blockDim.x + threadIdx.x;
    if (i < N) g_deg[i] = 0;

    if (blockIdx.x == 0) {
        __shared__ int bad;
        if (threadIdx.x == 0) bad = 0;
        __syncthreads();
        int limit = 1024 < 2 * E ? 1024 : 2 * E;
        for (int k = threadIdx.x; k < limit; k += blockDim.x) {
            long long v = e[k];
            if (v < 0 || v >= (long long)N) bad = 1;
        }
        __syncthreads();
        if (threadIdx.x == 0) g_idx64 = bad ? 0 : 1;
    }
}

// fp32 -> fp16 convert for the gather path
__global__ void convert_x_kernel(const float* __restrict__ x, int n4) {
    int i = blockIdx.x * blockDim.x + threadIdx.x;
    if (i >= n4) return;
    float4 v = reinterpret_cast<const float4*>(x)[i];
    __half2 p0 = __floats2half2_rn(v.x, v.y);
    __half2 p1 = __floats2half2_rn(v.z, v.w);
    uint2 pk;
    pk.x = *reinterpret_cast<uint32_t*>(&p0);
    pk.y = *reinterpret_cast<uint32_t*>(&p1);
    reinterpret_cast<uint2*>(g_xh)[i] = pk;
}

// ---------------------------------------------------------------------------
// CSR build: degree count -> exclusive scan -> fill permutation
// ---------------------------------------------------------------------------
__global__ void count_kernel(const void* __restrict__ eidx, int E, int N) {
    int e = blockIdx.x * blockDim.x + threadIdx.x;
    if (e >= E) return;
    int d = edge_at(eidx, e + E, N);
    atomicAdd(&g_deg[d], 1);
}

__global__ void scan1_kernel(int N) {
    __shared__ int sh[SCAN_BLK];
    int t = threadIdx.x;
    int i = blockIdx.x * SCAN_BLK + t;
    int v = (i < N) ? g_deg[i] : 0;
    sh[t] = v;
    __syncthreads();
#pragma unroll
    for (int ofs = 1; ofs < SCAN_BLK; ofs <<= 1) {
        int add = (t >= ofs) ? sh[t - ofs] : 0;
        __syncthreads();
        sh[t] += add;
        __syncthreads();
    }
    if (i < N) g_deg[i] = sh[t] - v;          // exclusive, in place
    if (t == SCAN_BLK - 1) g_part[blockIdx.x] = sh[t];
}

__global__ void scan2_kernel(int nb) {
    __shared__ int sh[128];
    int t = threadIdx.x;
    int v = (t < nb) ? g_part[t] : 0;
    sh[t] = v;
    __syncthreads();
#pragma unroll
    for (int ofs = 1; ofs < 128; ofs <<= 1) {
        int add = (t >= ofs) ? sh[t - ofs] : 0;
        __syncthreads();
        sh[t] += add;
        __syncthreads();
    }
    if (t < nb) g_part[t] = sh[t] - v;        // exclusive block offsets
}

__global__ void scan3_kernel(int N, int E) {
    int i = blockIdx.x * SCAN_BLK + threadIdx.x;
    if (i < N) {
        int r = g_deg[i] + g_part[i >> 9];    // SCAN_BLK == 512
        g_rowptr[i] = r;
        g_cursor[i] = r;
    }
    if (i == N) g_rowptr[N] = E;
}

__global__ void fill_kernel(const void* __restrict__ eidx, int E, int N) {
    int e = blockIdx.x * blockDim.x + threadIdx.x;
    if (e >= E) return;
    int s = edge_at(eidx, e, N);
    int d = edge_at(eidx, e + E, N);
    int pos = atomicAdd(&g_cursor[d], 1);
    g_perm[pos] = s;
}

// ---------------------------------------------------------------------------
// Gather aggregation (fp16 payload): one warp per dst node; lane owns 4 halves
// (8 bytes) of the 256-byte row. Accumulate fp32, write mean row once.
// ---------------------------------------------------------------------------
__global__ void __launch_bounds__(256)
agg_kernel(int N, int use_h) {
    int gw = (blockIdx.x * blockDim.x + threadIdx.x) >> 5;
    int lane = threadIdx.x & 31;
    if (gw >= N) return;

    const __half* __restrict__ X = use_h ? g_hh : g_xh;
    int beg = g_rowptr[gw];
    int end = g_rowptr[gw + 1];

    float a0 = 0.f, a1 = 0.f, a2 = 0.f, a3 = 0.f;
    for (int base = beg; base < end; base += 32) {
        int idx = base + lane;
        int sv = (idx < end) ? g_perm[idx] : 0;
        int m = min(32, end - base);
        for (int j = 0; j < m; j++) {
            int s = __shfl_sync(0xffffffffu, sv, j);
            uint2 pk = reinterpret_cast<const uint2*>(X + (size_t)s * D)[lane];
            __half2 h0 = *reinterpret_cast<__half2*>(&pk.x);
            __half2 h1 = *reinterpret_cast<__half2*>(&pk.y);
            float2 f0 = __half22float2(h0);
            float2 f1 = __half22float2(h1);
            a0 += f0.x; a1 += f0.y; a2 += f1.x; a3 += f1.y;
        }
    }
    float inv = (end > beg) ? 1.0f / (float)(end - beg) : 0.f;
    float4 o = make_float4(a0 * inv, a1 * inv, a2 * inv, a3 * inv);
    reinterpret_cast<float4*>(g_agg + (size_t)gw * D)[lane] = o;
}

// ---------------------------------------------------------------------------
// mma.sync bf16-split fused SAGE layer GEMM.
//   out[i,:] = g_agg[i,:] @ Wl^T + bias + X[i,:] @ Wr^T  (+ReLU)
// (g_agg already holds the neighbor MEAN.)
// ---------------------------------------------------------------------------
#define ROWB 144                 // smem row stride bytes (64 bf16 + 8 pad)
#define TILE_BYTES (128 * ROWB)  // 18432
#define SA_HI 0
#define SA_LO (SA_HI + TILE_BYTES)
#define SB_HI (SA_LO + TILE_BYTES)
#define SB_LO (SB_HI + TILE_BYTES)
#define SMEM_TOTAL (4 * TILE_BYTES)   // 73728

__device__ __forceinline__ void split_store(char* smem, int hi_off, int lo_off,
                                            int row, int col, float4 v) {
    __nv_bfloat16 h0 = __float2bfloat16(v.x);
    __nv_bfloat16 h1 = __float2bfloat16(v.y);
    __nv_bfloat16 h2 = __float2bfloat16(v.z);
    __nv_bfloat16 h3 = __float2bfloat16(v.w);
    __nv_bfloat16 l0 = __float2bfloat16(v.x - __bfloat162float(h0));
    __nv_bfloat16 l1 = __float2bfloat16(v.y - __bfloat162float(h1));
    __nv_bfloat16 l2 = __float2bfloat16(v.z - __bfloat162float(h2));
    __nv_bfloat16 l3 = __float2bfloat16(v.w - __bfloat162float(h3));
    uint2 hi, lo;
    hi.x = (uint32_t)__bfloat16_as_ushort(h0) | ((uint32_t)__bfloat16_as_ushort(h1) << 16);
    hi.y = (uint32_t)__bfloat16_as_ushort(h2) | ((uint32_t)__bfloat16_as_ushort(h3) << 16);
    lo.x = (uint32_t)__bfloat16_as_ushort(l0) | ((uint32_t)__bfloat16_as_ushort(l1) << 16);
    lo.y = (uint32_t)__bfloat16_as_ushort(l2) | ((uint32_t)__bfloat16_as_ushort(l3) << 16);
    int b = row * ROWB + col * 2;
    *reinterpret_cast<uint2*>(smem + hi_off + b) = hi;
    *reinterpret_cast<uint2*>(smem + lo_off + b) = lo;
}

__global__ void __launch_bounds__(256, 2)
sage_gemm_tc(const float* __restrict__ Xin,
             const float* __restrict__ Wl, const float* __restrict__ Wr,
             const float* __restrict__ bias,
             float* __restrict__ outp,
             int N, int relu, int x_is_h, int out_is_h) {
    extern __shared__ __align__(128) char smem[];
    uint32_t sb = smem_u32(smem);

    int tid = threadIdx.x, wid = tid >> 5, lane = tid & 31;
    int warpM = wid & 3, warpN = wid >> 2;
    int row0 = blockIdx.x * 128;

    const float* __restrict__ Xs = x_is_h ? g_h : Xin;
    float* __restrict__ out = out_is_h ? g_h : outp;

    uint32_t aoff[2], boff[4];
#pragma unroll
    for (int mi = 0; mi < 2; mi++)
        aoff[mi] = (uint32_t)((warpM * 32 + mi * 16 + (lane & 15)) * ROWB + (lane >> 4) * 16);
#pragma unroll
    for (int np = 0; np < 4; np++)
        boff[np] = (uint32_t)((warpN * 64 + np * 16 + (lane & 7) + ((lane & 16) ? 8 : 0)) * ROWB
                              + ((lane >> 3) & 1) * 16);

    float acc[2][8][4];
#pragma unroll
    for (int mi = 0; mi < 2; mi++)
#pragma unroll
        for (int ni = 0; ni < 8; ni++)
#pragma unroll
            for (int j = 0; j < 4; j++) acc[mi][ni][j] = 0.f;

    for (int c = 0; c < 4; c++) {
        const bool isAgg = (c < 2);
        const float* __restrict__ A = isAgg ? g_agg : Xs;
        const float* __restrict__ W = isAgg ? Wl : Wr;
        const int kb = (c & 1) * 64;

        if (c > 0) __syncthreads();

#pragma unroll
        for (int i = 0; i < 8; i++) {
            int f = i * 256 + tid;
            int r = f >> 4;
            int col = (f & 15) * 4;
            int row = row0 + r;
            float4 v = make_float4(0.f, 0.f, 0.f, 0.f);
            if (row < N)
                v = *reinterpret_cast<const float4*>(A + (size_t)row * D + kb + col);
            split_store(smem, SA_HI, SA_LO, r, col, v);

            float4 w = *reinterpret_cast<const float4*>(W + (size_t)r * D + kb + col);
            split_store(smem, SB_HI, SB_LO, r, col, w);
        }
        __syncthreads();

#pragma unroll
        for (int p = 0; p < 3; p++) {
            uint32_t abase = sb + ((p == 2) ? SA_LO : SA_HI);
            uint32_t bbase = sb + ((p == 1) ? SB_LO : SB_HI);
#pragma unroll
            for (int ks = 0; ks < 4; ks++) {
                uint32_t kbyte = (uint32_t)(ks * 32);
                uint32_t a[2][4], b[8][2];
#pragma unroll
                for (int mi = 0; mi < 2; mi++)
                    ldsm_x4(a[mi][0], a[mi][1], a[mi][2], a[mi][3],
                            abase + aoff[mi] + kbyte);
#pragma unroll
                for (int np = 0; np < 4; np++)
                    ldsm_x4(b[2 * np][0], b[2 * np][1], b[2 * np + 1][0], b[2 * np + 1][1],
                            bbase + boff[np] + kbyte);
#pragma unroll
                for (int mi = 0; mi < 2; mi++)
#pragma unroll
                    for (int ni = 0; ni < 8; ni++)
                        mma_bf16(acc[mi][ni], a[mi], b[ni]);
            }
        }
    }

    int g = lane >> 2, t = lane & 3;
#pragma unroll
    for (int mi = 0; mi < 2; mi++) {
        int r1 = row0 + warpM * 32 + mi * 16 + g;
        int r2 = r1 + 8;
#pragma unroll
        for (int ni = 0; ni < 8; ni++) {
            int col = warpN * 64 + ni * 8 + t * 2;
            float2 bs = *reinterpret_cast<const float2*>(bias + col);
            float2 o1, o2;
            o1.x = acc[mi][ni][0] + bs.x; o1.y = acc[mi][ni][1] + bs.y;
            o2.x = acc[mi][ni][2] + bs.x; o2.y = acc[mi][ni][3] + bs.y;
            if (relu) {
                o1.x = fmaxf(o1.x, 0.f); o1.y = fmaxf(o1.y, 0.f);
                o2.x = fmaxf(o2.x, 0.f); o2.y = fmaxf(o2.y, 0.f);
            }
            if (r1 < N) {
                *reinterpret_cast<float2*>(out + (size_t)r1 * D + col) = o1;
                if (out_is_h) {
                    __half2 p = __floats2half2_rn(o1.x, o1.y);
                    *reinterpret_cast<__half2*>(g_hh + (size_t)r1 * D + col) = p;
                }
            }
            if (r2 < N) {
                *reinterpret_cast<float2*>(out + (size_t)r2 * D + col) = o2;
                if (out_is_h) {
                    __half2 p = __floats2half2_rn(o2.x, o2.y);
                    *reinterpret_cast<__half2*>(g_hh + (size_t)r2 * D + col) = p;
                }
            }
        }
    }
}

// ---------------------------------------------------------------------------
extern "C" void kernel_launch(void* const* d_in, const int* in_sizes, int n_in,
                              void* d_out, int out_size) {
    const float* x   = (const float*)d_in[0];
    const void*  ei  = d_in[1];
    const float* Wl0 = (const float*)d_in[2];
    const float* bl0 = (const float*)d_in[3];
    const float* Wr0 = (const float*)d_in[4];
    const float* Wl1 = (const float*)d_in[5];
    const float* bl1 = (const float*)d_in[6];
    const float* Wr1 = (const float*)d_in[7];
    float*       out = (float*)d_out;

    int N = in_sizes[0] / D;
    int E = in_sizes[1] / 2;

    int n4          = N * (D / 4);
    int conv_blocks = (n4 + 255) / 256;
    int edge_blocks = (E + 255) / 256;
    int node_blocks = (N + 255) / 256;
    int scan_grid   = (N + SCAN_BLK - 1) / SCAN_BLK;
    int scan3_grid  = (N + 1 + SCAN_BLK - 1) / SCAN_BLK;
    int agg_blocks  = (N * 32 + 255) / 256;
    int gemm_blocks = (N + 127) / 128;

    cudaFuncSetAttribute(sage_gemm_tc,
                         cudaFuncAttributeMaxDynamicSharedMemorySize, SMEM_TOTAL);

    // CSR build + fp16 convert
    detect_zero_kernel<<<node_blocks, 256>>>((const long long*)ei, E, N);
    convert_x_kernel<<<conv_blocks, 256>>>(x, n4);
    count_kernel<<<edge_blocks, 256>>>(ei, E, N);
    scan1_kernel<<<scan_grid, SCAN_BLK>>>(N);
    scan2_kernel<<<1, 128>>>(scan_grid);
    scan3_kernel<<<scan3_grid, SCAN_BLK>>>(N, E);
    fill_kernel<<<edge_blocks, 256>>>(ei, E, N);

    // Layer 0
    agg_kernel<<<agg_blocks, 256>>>(N, /*use_h=*/0);
    sage_gemm_tc<<<gemm_blocks, 256, SMEM_TOTAL>>>(x, Wl0, Wr0, bl0, out, N,
                                                   /*relu=*/1, /*x_is_h=*/0, /*out_is_h=*/1);
    // Layer 1
    agg_kernel<<<agg_blocks, 256>>>(N, /*use_h=*/1);
    sage_gemm_tc<<<gemm_blocks, 256, SMEM_TOTAL>>>(x, Wl1, Wr1, bl1, out, N,
                                                   /*relu=*/0, /*x_is_h=*/1, /*out_is_h=*/0);
}

// round 7
// speedup vs baseline: 2.5658x; 1.0889x over previous
#include <cuda_runtime.h>
#include <cuda_bf16.h>
#include <cuda_fp16.h>
#include <cstdint>

#define D 128
#define MAXN 50000
#define NPAD 50176                 // padded rows so GEMM tail loads stay in-bounds
#define MAXE 800000
#define SCAN_BLK 512
#define SCAN_GRID ((MAXN + SCAN_BLK - 1) / SCAN_BLK)   // 98

// Scratch (device globals — no runtime allocation allowed)
__device__ __half        g_x16[(size_t)NPAD * D];   // fp16 x   (gather payload)
__device__ __half        g_h16[(size_t)NPAD * D];   // fp16 h   (gather payload)
__device__ __nv_bfloat16 g_xhi[(size_t)NPAD * D];   // bf16 split planes (GEMM A)
__device__ __nv_bfloat16 g_xlo[(size_t)NPAD * D];
__device__ __nv_bfloat16 g_hhi[(size_t)NPAD * D];
__device__ __nv_bfloat16 g_hlo[(size_t)NPAD * D];
__device__ __nv_bfloat16 g_ahi[(size_t)NPAD * D];   // agg mean, pre-split
__device__ __nv_bfloat16 g_alo[(size_t)NPAD * D];
__device__ __nv_bfloat16 g_whi[2 * 128 * 256];      // W planes [layer][n][k], k<128=Wl
__device__ __nv_bfloat16 g_wlo[2 * 128 * 256];
__device__ int    g_deg[MAXN];
__device__ int    g_part[SCAN_GRID];
__device__ int    g_rowptr[MAXN + 1];
__device__ int    g_cursor[MAXN];
__device__ int    g_perm[MAXE];
__device__ int    g_idx64;

// ---------------------------------------------------------------------------
__device__ __forceinline__ uint32_t smem_u32(const void* p) {
    uint32_t a;
    asm("{ .reg .u64 t; cvta.to.shared.u64 t, %1; cvt.u32.u64 %0, t; }"
        : "=r"(a) : "l"(p));
    return a;
}
__device__ __forceinline__ void ldsm_x4(uint32_t& r0, uint32_t& r1,
                                        uint32_t& r2, uint32_t& r3, uint32_t addr) {
    asm volatile("ldmatrix.sync.aligned.m8n8.x4.shared.b16 {%0,%1,%2,%3}, [%4];"
                 : "=r"(r0), "=r"(r1), "=r"(r2), "=r"(r3) : "r"(addr));
}
__device__ __forceinline__ void mma_bf16(float* c, const uint32_t* a, const uint32_t* b) {
    asm volatile(
        "mma.sync.aligned.m16n8k16.row.col.f32.bf16.bf16.f32 "
        "{%0,%1,%2,%3}, {%4,%5,%6,%7}, {%8,%9}, {%0,%1,%2,%3};"
        : "+f"(c[0]), "+f"(c[1]), "+f"(c[2]), "+f"(c[3])
        : "r"(a[0]), "r"(a[1]), "r"(a[2]), "r"(a[3]), "r"(b[0]), "r"(b[1]));
}
__device__ __forceinline__ uint32_t pack_bf2(__nv_bfloat16 a, __nv_bfloat16 b) {
    return (uint32_t)__bfloat16_as_ushort(a) | ((uint32_t)__bfloat16_as_ushort(b) << 16);
}

__device__ __forceinline__ int edge_at(const void* eidx, int i, int N) {
    long long v;
    if (g_idx64) v = ((const long long*)eidx)[i];
    else         v = ((const int*)eidx)[i];
    if (v < 0) v = 0;
    if (v >= N) v = N - 1;
    return (int)v;
}

// ---------------------------------------------------------------------------
// One-time weight split: W planes [layer][n=128][k=256] (k<128 -> Wl, else Wr)
// ---------------------------------------------------------------------------
__global__ void wsplit_kernel(const float* __restrict__ Wl0, const float* __restrict__ Wr0,
                              const float* __restrict__ Wl1, const float* __restrict__ Wr1) {
    int i = blockIdx.x * blockDim.x + threadIdx.x;
    if (i >= 2 * 128 * 256) return;
    int layer = i >> 15;
    int rem   = i & 32767;
    int n     = rem >> 8;
    int k     = rem & 255;
    const float* W = layer ? (k < 128 ? Wl1 : Wr1) : (k < 128 ? Wl0 : Wr0);
    float v = W[n * 128 + (k & 127)];
    __nv_bfloat16 h = __float2bfloat16(v);
    g_whi[i] = h;
    g_wlo[i] = __float2bfloat16(v - __bfloat162float(h));
}

// ---------------------------------------------------------------------------
// Detect edge-index dtype + zero degree array
// ---------------------------------------------------------------------------
__global__ void detect_zero_kernel(const long long* __restrict__ e, int E, int N) {
    int i = blockIdx.x * blockDim.x + threadIdx.x;
    if (i < N) g_deg[i] = 0;
    if (blockIdx.x == 0) {
        __shared__ int bad;
        if (threadIdx.x == 0) bad = 0;
        __syncthreads();
        int limit = 1024 < 2 * E ? 1024 : 2 * E;
        for (int k = threadIdx.x; k < limit; k += blockDim.x) {
            long long v = e[k];
            if (v < 0 || v >= (long long)N) bad = 1;
        }
        __syncthreads();
        if (threadIdx.x == 0) g_idx64 = bad ? 0 : 1;
    }
}

// fp32 x -> fp16 (gather) + bf16 hi/lo planes (GEMM)
__global__ void convert_x_kernel(const float* __restrict__ x, int n4) {
    int i = blockIdx.x * blockDim.x + threadIdx.x;
    if (i >= n4) return;
    float4 v = reinterpret_cast<const float4*>(x)[i];
    __half2 p0 = __floats2half2_rn(v.x, v.y);
    __half2 p1 = __floats2half2_rn(v.z, v.w);
    uint2 pk;
    pk.x = *reinterpret_cast<uint32_t*>(&p0);
    pk.y = *reinterpret_cast<uint32_t*>(&p1);
    reinterpret_cast<uint2*>(g_x16)[i] = pk;

    __nv_bfloat16 h0 = __float2bfloat16(v.x), h1 = __float2bfloat16(v.y);
    __nv_bfloat16 h2 = __float2bfloat16(v.z), h3 = __float2bfloat16(v.w);
    uint2 hi, lo;
    hi.x = pack_bf2(h0, h1); hi.y = pack_bf2(h2, h3);
    lo.x = pack_bf2(__float2bfloat16(v.x - __bfloat162float(h0)),
                    __float2bfloat16(v.y - __bfloat162float(h1)));
    lo.y = pack_bf2(__float2bfloat16(v.z - __bfloat162float(h2)),
                    __float2bfloat16(v.w - __bfloat162float(h3)));
    reinterpret_cast<uint2*>(g_xhi)[i] = hi;
    reinterpret_cast<uint2*>(g_xlo)[i] = lo;
}

// ---------------------------------------------------------------------------
// CSR build
// ---------------------------------------------------------------------------
__global__ void count_kernel(const void* __restrict__ eidx, int E, int N) {
    int e = blockIdx.x * blockDim.x + threadIdx.x;
    if (e >= E) return;
    atomicAdd(&g_deg[edge_at(eidx, e + E, N)], 1);
}

__global__ void scan1_kernel(int N) {
    __shared__ int sh[SCAN_BLK];
    int t = threadIdx.x;
    int i = blockIdx.x * SCAN_BLK + t;
    int v = (i < N) ? g_deg[i] : 0;
    sh[t] = v;
    __syncthreads();
#pragma unroll
    for (int ofs = 1; ofs < SCAN_BLK; ofs <<= 1) {
        int add = (t >= ofs) ? sh[t - ofs] : 0;
        __syncthreads();
        sh[t] += add;
        __syncthreads();
    }
    if (i < N) g_deg[i] = sh[t] - v;
    if (t == SCAN_BLK - 1) g_part[blockIdx.x] = sh[t];
}

__global__ void scan2_kernel(int nb) {
    __shared__ int sh[128];
    int t = threadIdx.x;
    int v = (t < nb) ? g_part[t] : 0;
    sh[t] = v;
    __syncthreads();
#pragma unroll
    for (int ofs = 1; ofs < 128; ofs <<= 1) {
        int add = (t >= ofs) ? sh[t - ofs] : 0;
        __syncthreads();
        sh[t] += add;
        __syncthreads();
    }
    if (t < nb) g_part[t] = sh[t] - v;
}

__global__ void scan3_kernel(int N, int E) {
    int i = blockIdx.x * SCAN_BLK + threadIdx.x;
    if (i < N) {
        int r = g_deg[i] + g_part[i >> 9];
        g_rowptr[i] = r;
        g_cursor[i] = r;
    }
    if (i == N) g_rowptr[N] = E;
}

__global__ void fill_kernel(const void* __restrict__ eidx, int E, int N) {
    int e = blockIdx.x * blockDim.x + threadIdx.x;
    if (e >= E) return;
    int s = edge_at(eidx, e, N);
    int d = edge_at(eidx, e + E, N);
    g_perm[atomicAdd(&g_cursor[d], 1)] = s;
}

// ---------------------------------------------------------------------------
// Gather aggregation (fp16 payload): one warp per dst node; mean written
// directly as bf16 hi/lo planes for the GEMM.
// ---------------------------------------------------------------------------
__global__ void __launch_bounds__(256)
agg_kernel(int N, int use_h) {
    int gw = (blockIdx.x * blockDim.x + threadIdx.x) >> 5;
    int lane = threadIdx.x & 31;
    if (gw >= N) return;

    const __half* __restrict__ X = use_h ? g_h16 : g_x16;
    int beg = g_rowptr[gw];
    int end = g_rowptr[gw + 1];

    float a0 = 0.f, a1 = 0.f, a2 = 0.f, a3 = 0.f;
    for (int base = beg; base < end; base += 32) {
        int idx = base + lane;
        int sv = (idx < end) ? g_perm[idx] : 0;
        int m = min(32, end - base);
        for (int j = 0; j < m; j++) {
            int s = __shfl_sync(0xffffffffu, sv, j);
            uint2 pk = reinterpret_cast<const uint2*>(X + (size_t)s * D)[lane];
            __half2 h0 = *reinterpret_cast<__half2*>(&pk.x);
            __half2 h1 = *reinterpret_cast<__half2*>(&pk.y);
            float2 f0 = __half22float2(h0);
            float2 f1 = __half22float2(h1);
            a0 += f0.x; a1 += f0.y; a2 += f1.x; a3 += f1.y;
        }
    }
    float inv = (end > beg) ? 1.0f / (float)(end - beg) : 0.f;
    float v0 = a0 * inv, v1 = a1 * inv, v2 = a2 * inv, v3 = a3 * inv;

    __nv_bfloat16 h0 = __float2bfloat16(v0), h1 = __float2bfloat16(v1);
    __nv_bfloat16 h2 = __float2bfloat16(v2), h3 = __float2bfloat16(v3);
    uint2 hi, lo;
    hi.x = pack_bf2(h0, h1); hi.y = pack_bf2(h2, h3);
    lo.x = pack_bf2(__float2bfloat16(v0 - __bfloat162float(h0)),
                    __float2bfloat16(v1 - __bfloat162float(h1)));
    lo.y = pack_bf2(__float2bfloat16(v2 - __bfloat162float(h2)),
                    __float2bfloat16(v3 - __bfloat162float(h3)));
    reinterpret_cast<uint2*>(g_ahi + (size_t)gw * D)[lane] = hi;
    reinterpret_cast<uint2*>(g_alo + (size_t)gw * D)[lane] = lo;
}

// ---------------------------------------------------------------------------
// mma.sync bf16-split fused SAGE layer GEMM — conversion-free mainloop.
// All operands arrive pre-split as bf16 hi/lo planes; the loader is a pure
// uint4 gmem->smem copy. 3 passes: Ahi*Bhi + Ahi*Blo + Alo*Bhi.
// ---------------------------------------------------------------------------
#define ROWB 144
#define TILE_BYTES (128 * ROWB)
#define SA_HI 0
#define SA_LO (SA_HI + TILE_BYTES)
#define SB_HI (SA_LO + TILE_BYTES)
#define SB_LO (SB_HI + TILE_BYTES)
#define SMEM_TOTAL (4 * TILE_BYTES)   // 73728

__global__ void __launch_bounds__(256, 2)
sage_gemm_tc(const float* __restrict__ bias,
             float* __restrict__ outp,
             int N, int layer) {
    extern __shared__ __align__(128) char smem[];
    uint32_t sb = smem_u32(smem);

    int tid = threadIdx.x, wid = tid >> 5, lane = tid & 31;
    int warpM = wid & 3, warpN = wid >> 2;
    int row0 = blockIdx.x * 128;
    int relu = (layer == 0);

    uint32_t aoff[2], boff[4];
#pragma unroll
    for (int mi = 0; mi < 2; mi++)
        aoff[mi] = (uint32_t)((warpM * 32 + mi * 16 + (lane & 15)) * ROWB + (lane >> 4) * 16);
#pragma unroll
    for (int np = 0; np < 4; np++)
        boff[np] = (uint32_t)((warpN * 64 + np * 16 + (lane & 7) + ((lane & 16) ? 8 : 0)) * ROWB
                              + ((lane >> 3) & 1) * 16);

    float acc[2][8][4];
#pragma unroll
    for (int mi = 0; mi < 2; mi++)
#pragma unroll
        for (int ni = 0; ni < 8; ni++)
#pragma unroll
            for (int j = 0; j < 4; j++) acc[mi][ni][j] = 0.f;

    for (int c = 0; c < 4; c++) {
        const __nv_bfloat16* __restrict__ Ah;
        const __nv_bfloat16* __restrict__ Al;
        if (c < 2) { Ah = g_ahi; Al = g_alo; }
        else       { Ah = layer ? g_hhi : g_xhi; Al = layer ? g_hlo : g_xlo; }
        const int kb = (c & 1) * 64;

        if (c > 0) __syncthreads();

#pragma unroll
        for (int i = 0; i < 4; i++) {
            int f = i * 256 + tid;    // uint4 index 0..1023
            int r = f >> 3;           // row 0..127
            int c8 = (f & 7) * 8;     // bf16 col offset 0..56
            int sm = r * ROWB + c8 * 2;

            size_t ga = (size_t)(row0 + r) * D + kb + c8;
            *reinterpret_cast<uint4*>(smem + SA_HI + sm) =
                *reinterpret_cast<const uint4*>(Ah + ga);
            *reinterpret_cast<uint4*>(smem + SA_LO + sm) =
                *reinterpret_cast<const uint4*>(Al + ga);

            size_t gb = ((size_t)layer * 128 + r) * 256 + c * 64 + c8;
            *reinterpret_cast<uint4*>(smem + SB_HI + sm) =
                *reinterpret_cast<const uint4*>(g_whi + gb);
            *reinterpret_cast<uint4*>(smem + SB_LO + sm) =
                *reinterpret_cast<const uint4*>(g_wlo + gb);
        }
        __syncthreads();

#pragma unroll
        for (int p = 0; p < 3; p++) {
            uint32_t abase = sb + ((p == 2) ? SA_LO : SA_HI);
            uint32_t bbase = sb + ((p == 1) ? SB_LO : SB_HI);
#pragma unroll
            for (int ks = 0; ks < 4; ks++) {
                uint32_t kbyte = (uint32_t)(ks * 32);
                uint32_t a[2][4], b[8][2];
#pragma unroll
                for (int mi = 0; mi < 2; mi++)
                    ldsm_x4(a[mi][0], a[mi][1], a[mi][2], a[mi][3],
                            abase + aoff[mi] + kbyte);
#pragma unroll
                for (int np = 0; np < 4; np++)
                    ldsm_x4(b[2 * np][0], b[2 * np][1], b[2 * np + 1][0], b[2 * np + 1][1],
                            bbase + boff[np] + kbyte);
#pragma unroll
                for (int mi = 0; mi < 2; mi++)
#pragma unroll
                    for (int ni = 0; ni < 8; ni++)
                        mma_bf16(acc[mi][ni], a[mi], b[ni]);
            }
        }
    }

    int g = lane >> 2, t = lane & 3;
#pragma unroll
    for (int mi = 0; mi < 2; mi++) {
        int r1 = row0 + warpM * 32 + mi * 16 + g;
        int r2 = r1 + 8;
#pragma unroll
        for (int ni = 0; ni < 8; ni++) {
            int col = warpN * 64 + ni * 8 + t * 2;
            float2 bs = *reinterpret_cast<const float2*>(bias + col);
            float2 o1, o2;
            o1.x = acc[mi][ni][0] + bs.x; o1.y = acc[mi][ni][1] + bs.y;
            o2.x = acc[mi][ni][2] + bs.x; o2.y = acc[mi][ni][3] + bs.y;
            if (relu) {
                o1.x = fmaxf(o1.x, 0.f); o1.y = fmaxf(o1.y, 0.f);
                o2.x = fmaxf(o2.x, 0.f); o2.y = fmaxf(o2.y, 0.f);
            }
            if (layer == 0) {
                // write h as fp16 (gather) + bf16 hi/lo planes (GEMM-1 A operand)
                if (r1 < N) {
                    size_t o = (size_t)r1 * D + col;
                    __half2 p = __floats2half2_rn(o1.x, o1.y);
                    *reinterpret_cast<__half2*>(g_h16 + o) = p;
                    __nv_bfloat16 b0 = __float2bfloat16(o1.x), b1 = __float2bfloat16(o1.y);
                    *reinterpret_cast<uint32_t*>(g_hhi + o) = pack_bf2(b0, b1);
                    *reinterpret_cast<uint32_t*>(g_hlo + o) =
                        pack_bf2(__float2bfloat16(o1.x - __bfloat162float(b0)),
                                 __float2bfloat16(o1.y - __bfloat162float(b1)));
                }
                if (r2 < N) {
                    size_t o = (size_t)r2 * D + col;
                    __half2 p = __floats2half2_rn(o2.x, o2.y);
                    *reinterpret_cast<__half2*>(g_h16 + o) = p;
                    __nv_bfloat16 b0 = __float2bfloat16(o2.x), b1 = __float2bfloat16(o2.y);
                    *reinterpret_cast<uint32_t*>(g_hhi + o) = pack_bf2(b0, b1);
                    *reinterpret_cast<uint32_t*>(g_hlo + o) =
                        pack_bf2(__float2bfloat16(o2.x - __bfloat162float(b0)),
                                 __float2bfloat16(o2.y - __bfloat162float(b1)));
                }
            } else {
                if (r1 < N) *reinterpret_cast<float2*>(outp + (size_t)r1 * D + col) = o1;
                if (r2 < N) *reinterpret_cast<float2*>(outp + (size_t)r2 * D + col) = o2;
            }
        }
    }
}

// ---------------------------------------------------------------------------
extern "C" void kernel_launch(void* const* d_in, const int* in_sizes, int n_in,
                              void* d_out, int out_size) {
    const float* x   = (const float*)d_in[0];
    const void*  ei  = d_in[1];
    const float* Wl0 = (const float*)d_in[2];
    const float* bl0 = (const float*)d_in[3];
    const float* Wr0 = (const float*)d_in[4];
    const float* Wl1 = (const float*)d_in[5];
    const float* bl1 = (const float*)d_in[6];
    const float* Wr1 = (const float*)d_in[7];
    float*       out = (float*)d_out;

    int N = in_sizes[0] / D;
    int E = in_sizes[1] / 2;

    int n4          = N * (D / 4);
    int conv_blocks = (n4 + 255) / 256;
    int edge_blocks = (E + 255) / 256;
    int node_blocks = (N + 255) / 256;
    int scan_grid   = (N + SCAN_BLK - 1) / SCAN_BLK;
    int scan3_grid  = (N + 1 + SCAN_BLK - 1) / SCAN_BLK;
    int agg_blocks  = (N * 32 + 255) / 256;
    int gemm_blocks = (N + 127) / 128;

    cudaFuncSetAttribute(sage_gemm_tc,
                         cudaFuncAttributeMaxDynamicSharedMemorySize, SMEM_TOTAL);

    // One-time prep + CSR build
    wsplit_kernel<<<256, 256>>>(Wl0, Wr0, Wl1, Wr1);
    detect_zero_kernel<<<node_blocks, 256>>>((const long long*)ei, E, N);
    convert_x_kernel<<<conv_blocks, 256>>>(x, n4);
    count_kernel<<<edge_blocks, 256>>>(ei, E, N);
    scan1_kernel<<<scan_grid, SCAN_BLK>>>(N);
    scan2_kernel<<<1, 128>>>(scan_grid);
    scan3_kernel<<<scan3_grid, SCAN_BLK>>>(N, E);
    fill_kernel<<<edge_blocks, 256>>>(ei, E, N);

    // Layer 0
    agg_kernel<<<agg_blocks, 256>>>(N, /*use_h=*/0);
    sage_gemm_tc<<<gemm_blocks, 256, SMEM_TOTAL>>>(bl0, out, N, /*layer=*/0);
    // Layer 1
    agg_kernel<<<agg_blocks, 256>>>(N, /*use_h=*/1);
    sage_gemm_tc<<<gemm_blocks, 256, SMEM_TOTAL>>>(bl1, out, N, /*layer=*/1);
}

// round 8
// speedup vs baseline: 2.6749x; 1.0425x over previous
#include <cuda_runtime.h>
#include <cuda_bf16.h>
#include <cuda_fp16.h>
#include <cstdint>

#define D 128
#define MAXN 50000
#define NPAD 50176                 // padded rows so GEMM tail loads stay in-bounds
#define MAXE 800000
#define SCAN_BLK 512
#define SCAN_GRID ((MAXN + SCAN_BLK - 1) / SCAN_BLK)   // 98

// Scratch (device globals — no runtime allocation allowed)
__device__ __half g_x16[(size_t)NPAD * D];   // fp16 x (gather + GEMM A)
__device__ __half g_h16[(size_t)NPAD * D];   // fp16 h (gather + GEMM A)
__device__ __half g_a16[(size_t)NPAD * D];   // fp16 agg mean (GEMM A)
__device__ __half g_whi[2 * 128 * 256];      // fp16 W split planes [layer][n][k]
__device__ __half g_wlo[2 * 128 * 256];      // (k<128 -> Wl, k>=128 -> Wr)
__device__ int    g_deg[MAXN];
__device__ int    g_part[SCAN_GRID];
__device__ int    g_rowptr[MAXN + 1];
__device__ int    g_cursor[MAXN];
__device__ int    g_perm[MAXE];
__device__ int    g_idx64;

// ---------------------------------------------------------------------------
__device__ __forceinline__ uint32_t smem_u32(const void* p) {
    uint32_t a;
    asm("{ .reg .u64 t; cvta.to.shared.u64 t, %1; cvt.u32.u64 %0, t; }"
        : "=r"(a) : "l"(p));
    return a;
}
__device__ __forceinline__ void ldsm_x4(uint32_t& r0, uint32_t& r1,
                                        uint32_t& r2, uint32_t& r3, uint32_t addr) {
    asm volatile("ldmatrix.sync.aligned.m8n8.x4.shared.b16 {%0,%1,%2,%3}, [%4];"
                 : "=r"(r0), "=r"(r1), "=r"(r2), "=r"(r3) : "r"(addr));
}
__device__ __forceinline__ void mma_fp16(float* c, const uint32_t* a, const uint32_t* b) {
    asm volatile(
        "mma.sync.aligned.m16n8k16.row.col.f32.f16.f16.f32 "
        "{%0,%1,%2,%3}, {%4,%5,%6,%7}, {%8,%9}, {%0,%1,%2,%3};"
        : "+f"(c[0]), "+f"(c[1]), "+f"(c[2]), "+f"(c[3])
        : "r"(a[0]), "r"(a[1]), "r"(a[2]), "r"(a[3]), "r"(b[0]), "r"(b[1]));
}

__device__ __forceinline__ int clampN(long long v, int N) {
    if (v < 0) v = 0;
    if (v >= N) v = N - 1;
    return (int)v;
}

// ---------------------------------------------------------------------------
// One-time weight split: fp16 planes [layer][n=128][k=256]
// ---------------------------------------------------------------------------
__global__ void wsplit_kernel(const float* __restrict__ Wl0, const float* __restrict__ Wr0,
                              const float* __restrict__ Wl1, const float* __restrict__ Wr1) {
    int i = blockIdx.x * blockDim.x + threadIdx.x;
    if (i >= 2 * 128 * 256) return;
    int layer = i >> 15;
    int rem   = i & 32767;
    int n     = rem >> 8;
    int k     = rem & 255;
    const float* W = layer ? (k < 128 ? Wl1 : Wr1) : (k < 128 ? Wl0 : Wr0);
    float v = W[n * 128 + (k & 127)];
    __half h = __float2half_rn(v);
    g_whi[i] = h;
    g_wlo[i] = __float2half_rn(v - __half2float(h));
}

// ---------------------------------------------------------------------------
// Detect edge-index dtype + zero degree array
// ---------------------------------------------------------------------------
__global__ void detect_zero_kernel(const long long* __restrict__ e, int E, int N) {
    int i = blockIdx.x * blockDim.x + threadIdx.x;
    if (i < N) g_deg[i] = 0;
    if (blockIdx.x == 0) {
        __shared__ int bad;
        if (threadIdx.x == 0) bad = 0;
        __syncthreads();
        int limit = 1024 < 2 * E ? 1024 : 2 * E;
        for (int k = threadIdx.x; k < limit; k += blockDim.x) {
            long long v = e[k];
            if (v < 0 || v >= (long long)N) bad = 1;
        }
        __syncthreads();
        if (threadIdx.x == 0) g_idx64 = bad ? 0 : 1;
    }
}

// fp32 x -> fp16
__global__ void convert_x_kernel(const float* __restrict__ x, int n4) {
    int i = blockIdx.x * blockDim.x + threadIdx.x;
    if (i >= n4) return;
    float4 v = reinterpret_cast<const float4*>(x)[i];
    __half2 p0 = __floats2half2_rn(v.x, v.y);
    __half2 p1 = __floats2half2_rn(v.z, v.w);
    uint2 pk;
    pk.x = *reinterpret_cast<uint32_t*>(&p0);
    pk.y = *reinterpret_cast<uint32_t*>(&p1);
    reinterpret_cast<uint2*>(g_x16)[i] = pk;
}

// ---------------------------------------------------------------------------
// CSR build — edge kernels batched 4 edges/thread (MLP=4, vector index loads)
// ---------------------------------------------------------------------------
__global__ void count_kernel(const void* __restrict__ eidx, int E, int N) {
    int t = blockIdx.x * blockDim.x + threadIdx.x;
    int e0 = t * 4;
    if (e0 >= E) return;
    int d0, d1, d2, d3;
    int m = E - e0;
    if (g_idx64) {
        const long long* ei = (const long long*)eidx + E;   // dst row
        longlong2 p0, p1;
        if (m >= 4) {
            p0 = *reinterpret_cast<const longlong2*>(ei + e0);
            p1 = *reinterpret_cast<const longlong2*>(ei + e0 + 2);
        } else {
            p0.x = ei[e0]; p0.y = (m > 1) ? ei[e0 + 1] : ei[e0];
            p1.x = (m > 2) ? ei[e0 + 2] : ei[e0]; p1.y = p1.x;
        }
        d0 = clampN(p0.x, N); d1 = clampN(p0.y, N);
        d2 = clampN(p1.x, N); d3 = clampN(p1.y, N);
    } else {
        const int* ei = (const int*)eidx + E;
        int4 p;
        if (m >= 4) p = *reinterpret_cast<const int4*>(ei + e0);
        else {
            p.x = ei[e0]; p.y = (m > 1) ? ei[e0 + 1] : p.x;
            p.z = (m > 2) ? ei[e0 + 2] : p.x; p.w = p.z;
        }
        d0 = clampN(p.x, N); d1 = clampN(p.y, N);
        d2 = clampN(p.z, N); d3 = clampN(p.w, N);
    }
    atomicAdd(&g_deg[d0], 1);
    if (m > 1) atomicAdd(&g_deg[d1], 1);
    if (m > 2) atomicAdd(&g_deg[d2], 1);
    if (m > 3) atomicAdd(&g_deg[d3], 1);
}

__global__ void scan1_kernel(int N) {
    __shared__ int sh[SCAN_BLK];
    int t = threadIdx.x;
    int i = blockIdx.x * SCAN_BLK + t;
    int v = (i < N) ? g_deg[i] : 0;
    sh[t] = v;
    __syncthreads();
#pragma unroll
    for (int ofs = 1; ofs < SCAN_BLK; ofs <<= 1) {
        int add = (t >= ofs) ? sh[t - ofs] : 0;
        __syncthreads();
        sh[t] += add;
        __syncthreads();
    }
    if (i < N) g_deg[i] = sh[t] - v;
    if (t == SCAN_BLK - 1) g_part[blockIdx.x] = sh[t];
}

__global__ void scan2_kernel(int nb) {
    __shared__ int sh[128];
    int t = threadIdx.x;
    int v = (t < nb) ? g_part[t] : 0;
    sh[t] = v;
    __syncthreads();
#pragma unroll
    for (int ofs = 1; ofs < 128; ofs <<= 1) {
        int add = (t >= ofs) ? sh[t - ofs] : 0;
        __syncthreads();
        sh[t] += add;
        __syncthreads();
    }
    if (t < nb) g_part[t] = sh[t] - v;
}

__global__ void scan3_kernel(int N, int E) {
    int i = blockIdx.x * SCAN_BLK + threadIdx.x;
    if (i < N) {
        int r = g_deg[i] + g_part[i >> 9];
        g_rowptr[i] = r;
        g_cursor[i] = r;
    }
    if (i == N) g_rowptr[N] = E;
}

__global__ void fill_kernel(const void* __restrict__ eidx, int E, int N) {
    int t = blockIdx.x * blockDim.x + threadIdx.x;
    int e0 = t * 4;
    if (e0 >= E) return;
    int m = E - e0;
    int s[4], d[4];
    if (g_idx64) {
        const long long* es = (const long long*)eidx;
        const long long* ed = es + E;
#pragma unroll
        for (int j = 0; j < 4; j++) {
            int e = (j < m) ? e0 + j : e0;
            s[j] = clampN(es[e], N);
            d[j] = clampN(ed[e], N);
        }
    } else {
        const int* es = (const int*)eidx;
        const int* ed = es + E;
        if (m >= 4) {
            int4 ps = *reinterpret_cast<const int4*>(es + e0);
            int4 pd = *reinterpret_cast<const int4*>(ed + e0);
            s[0] = clampN(ps.x, N); s[1] = clampN(ps.y, N);
            s[2] = clampN(ps.z, N); s[3] = clampN(ps.w, N);
            d[0] = clampN(pd.x, N); d[1] = clampN(pd.y, N);
            d[2] = clampN(pd.z, N); d[3] = clampN(pd.w, N);
        } else {
#pragma unroll
            for (int j = 0; j < 4; j++) {
                int e = (j < m) ? e0 + j : e0;
                s[j] = clampN(es[e], N);
                d[j] = clampN(ed[e], N);
            }
        }
    }
#pragma unroll
    for (int j = 0; j < 4; j++)
        if (j < m) g_perm[atomicAdd(&g_cursor[d[j]], 1)] = s[j];
}

// ---------------------------------------------------------------------------
// Gather aggregation (fp16): one warp per dst node; mean written as fp16.
// ---------------------------------------------------------------------------
__global__ void __launch_bounds__(256)
agg_kernel(int N, int use_h) {
    int gw = (blockIdx.x * blockDim.x + threadIdx.x) >> 5;
    int lane = threadIdx.x & 31;
    if (gw >= N) return;

    const __half* __restrict__ X = use_h ? g_h16 : g_x16;
    int beg = g_rowptr[gw];
    int end = g_rowptr[gw + 1];

    float a0 = 0.f, a1 = 0.f, a2 = 0.f, a3 = 0.f;
    for (int base = beg; base < end; base += 32) {
        int idx = base + lane;
        int sv = (idx < end) ? g_perm[idx] : 0;
        int m = min(32, end - base);
        for (int j = 0; j < m; j++) {
            int s = __shfl_sync(0xffffffffu, sv, j);
            uint2 pk = reinterpret_cast<const uint2*>(X + (size_t)s * D)[lane];
            __half2 h0 = *reinterpret_cast<__half2*>(&pk.x);
            __half2 h1 = *reinterpret_cast<__half2*>(&pk.y);
            float2 f0 = __half22float2(h0);
            float2 f1 = __half22float2(h1);
            a0 += f0.x; a1 += f0.y; a2 += f1.x; a3 += f1.y;
        }
    }
    float inv = (end > beg) ? 1.0f / (float)(end - beg) : 0.f;
    __half2 p0 = __floats2half2_rn(a0 * inv, a1 * inv);
    __half2 p1 = __floats2half2_rn(a2 * inv, a3 * inv);
    uint2 pk;
    pk.x = *reinterpret_cast<uint32_t*>(&p0);
    pk.y = *reinterpret_cast<uint32_t*>(&p1);
    reinterpret_cast<uint2*>(g_a16 + (size_t)gw * D)[lane] = pk;
}

// ---------------------------------------------------------------------------
// fp16 2-pass fused SAGE layer GEMM:  D = A*Whi + A*Wlo  (W split exact).
// A is fp16 single-plane (agg for k<128, x/h for k>=128). A-ldsm regs are
// reused across both W passes.
// ---------------------------------------------------------------------------
#define ROWB 144
#define TILE_BYTES (128 * ROWB)
#define SA    0
#define SB_HI (SA + TILE_BYTES)
#define SB_LO (SB_HI + TILE_BYTES)
#define SMEM_TOTAL (3 * TILE_BYTES)   // 55296

__global__ void __launch_bounds__(256, 3)
sage_gemm_tc(const float* __restrict__ bias,
             float* __restrict__ outp,
             int N, int layer) {
    extern __shared__ __align__(128) char smem[];
    uint32_t sb = smem_u32(smem);

    int tid = threadIdx.x, wid = tid >> 5, lane = tid & 31;
    int warpM = wid & 3, warpN = wid >> 2;
    int row0 = blockIdx.x * 128;
    int relu = (layer == 0);

    uint32_t aoff[2], boff[4];
#pragma unroll
    for (int mi = 0; mi < 2; mi++)
        aoff[mi] = (uint32_t)((warpM * 32 + mi * 16 + (lane & 15)) * ROWB + (lane >> 4) * 16);
#pragma unroll
    for (int np = 0; np < 4; np++)
        boff[np] = (uint32_t)((warpN * 64 + np * 16 + (lane & 7) + ((lane & 16) ? 8 : 0)) * ROWB
                              + ((lane >> 3) & 1) * 16);

    float acc[2][8][4];
#pragma unroll
    for (int mi = 0; mi < 2; mi++)
#pragma unroll
        for (int ni = 0; ni < 8; ni++)
#pragma unroll
            for (int j = 0; j < 4; j++) acc[mi][ni][j] = 0.f;

    for (int c = 0; c < 4; c++) {
        const __half* __restrict__ A =
            (c < 2) ? g_a16 : (layer ? g_h16 : g_x16);
        const int kb = (c & 1) * 64;

        if (c > 0) __syncthreads();

#pragma unroll
        for (int i = 0; i < 4; i++) {
            int f = i * 256 + tid;    // uint4 index 0..1023
            int r = f >> 3;           // row 0..127
            int c8 = (f & 7) * 8;     // fp16 col offset 0..56
            int sm = r * ROWB + c8 * 2;

            *reinterpret_cast<uint4*>(smem + SA + sm) =
                *reinterpret_cast<const uint4*>(A + (size_t)(row0 + r) * D + kb + c8);

            size_t gb = ((size_t)layer * 128 + r) * 256 + c * 64 + c8;
            *reinterpret_cast<uint4*>(smem + SB_HI + sm) =
                *reinterpret_cast<const uint4*>(g_whi + gb);
            *reinterpret_cast<uint4*>(smem + SB_LO + sm) =
                *reinterpret_cast<const uint4*>(g_wlo + gb);
        }
        __syncthreads();

#pragma unroll
        for (int ks = 0; ks < 4; ks++) {
            uint32_t kbyte = (uint32_t)(ks * 32);
            uint32_t a[2][4], b[8][2];
#pragma unroll
            for (int mi = 0; mi < 2; mi++)
                ldsm_x4(a[mi][0], a[mi][1], a[mi][2], a[mi][3],
                        sb + SA + aoff[mi] + kbyte);
            // pass 1: W_hi
#pragma unroll
            for (int np = 0; np < 4; np++)
                ldsm_x4(b[2 * np][0], b[2 * np][1], b[2 * np + 1][0], b[2 * np + 1][1],
                        sb + SB_HI + boff[np] + kbyte);
#pragma unroll
            for (int mi = 0; mi < 2; mi++)
#pragma unroll
                for (int ni = 0; ni < 8; ni++)
                    mma_fp16(acc[mi][ni], a[mi], b[ni]);
            // pass 2: W_lo (A regs reused)
#pragma unroll
            for (int np = 0; np < 4; np++)
                ldsm_x4(b[2 * np][0], b[2 * np][1], b[2 * np + 1][0], b[2 * np + 1][1],
                        sb + SB_LO + boff[np] + kbyte);
#pragma unroll
            for (int mi = 0; mi < 2; mi++)
#pragma unroll
                for (int ni = 0; ni < 8; ni++)
                    mma_fp16(acc[mi][ni], a[mi], b[ni]);
        }
    }

    int g = lane >> 2, t = lane & 3;
#pragma unroll
    for (int mi = 0; mi < 2; mi++) {
        int r1 = row0 + warpM * 32 + mi * 16 + g;
        int r2 = r1 + 8;
#pragma unroll
        for (int ni = 0; ni < 8; ni++) {
            int col = warpN * 64 + ni * 8 + t * 2;
            float2 bs = *reinterpret_cast<const float2*>(bias + col);
            float2 o1, o2;
            o1.x = acc[mi][ni][0] + bs.x; o1.y = acc[mi][ni][1] + bs.y;
            o2.x = acc[mi][ni][2] + bs.x; o2.y = acc[mi][ni][3] + bs.y;
            if (relu) {
                o1.x = fmaxf(o1.x, 0.f); o1.y = fmaxf(o1.y, 0.f);
                o2.x = fmaxf(o2.x, 0.f); o2.y = fmaxf(o2.y, 0.f);
            }
            if (layer == 0) {
                if (r1 < N) {
                    __half2 p = __floats2half2_rn(o1.x, o1.y);
                    *reinterpret_cast<__half2*>(g_h16 + (size_t)r1 * D + col) = p;
                }
                if (r2 < N) {
                    __half2 p = __floats2half2_rn(o2.x, o2.y);
                    *reinterpret_cast<__half2*>(g_h16 + (size_t)r2 * D + col) = p;
                }
            } else {
                if (r1 < N) *reinterpret_cast<float2*>(outp + (size_t)r1 * D + col) = o1;
                if (r2 < N) *reinterpret_cast<float2*>(outp + (size_t)r2 * D + col) = o2;
            }
        }
    }
}

// ---------------------------------------------------------------------------
extern "C" void kernel_launch(void* const* d_in, const int* in_sizes, int n_in,
                              void* d_out, int out_size) {
    const float* x   = (const float*)d_in[0];
    const void*  ei  = d_in[1];
    const float* Wl0 = (const float*)d_in[2];
    const float* bl0 = (const float*)d_in[3];
    const float* Wr0 = (const float*)d_in[4];
    const float* Wl1 = (const float*)d_in[5];
    const float* bl1 = (const float*)d_in[6];
    const float* Wr1 = (const float*)d_in[7];
    float*       out = (float*)d_out;

    int N = in_sizes[0] / D;
    int E = in_sizes[1] / 2;

    int n4          = N * (D / 4);
    int conv_blocks = (n4 + 255) / 256;
    int edge4_blocks = ((E + 3) / 4 + 255) / 256;
    int node_blocks = (N + 255) / 256;
    int scan_grid   = (N + SCAN_BLK - 1) / SCAN_BLK;
    int scan3_grid  = (N + 1 + SCAN_BLK - 1) / SCAN_BLK;
    int agg_blocks  = (N * 32 + 255) / 256;
    int gemm_blocks = (N + 127) / 128;

    cudaFuncSetAttribute(sage_gemm_tc,
                         cudaFuncAttributeMaxDynamicSharedMemorySize, SMEM_TOTAL);

    // One-time prep + CSR build
    wsplit_kernel<<<256, 256>>>(Wl0, Wr0, Wl1, Wr1);
    detect_zero_kernel<<<node_blocks, 256>>>((const long long*)ei, E, N);
    convert_x_kernel<<<conv_blocks, 256>>>(x, n4);
    count_kernel<<<edge4_blocks, 256>>>(ei, E, N);
    scan1_kernel<<<scan_grid, SCAN_BLK>>>(N);
    scan2_kernel<<<1, 128>>>(scan_grid);
    scan3_kernel<<<scan3_grid, SCAN_BLK>>>(N, E);
    fill_kernel<<<edge4_blocks, 256>>>(ei, E, N);

    // Layer 0
    agg_kernel<<<agg_blocks, 256>>>(N, /*use_h=*/0);
    sage_gemm_tc<<<gemm_blocks, 256, SMEM_TOTAL>>>(bl0, out, N, /*layer=*/0);
    // Layer 1
    agg_kernel<<<agg_blocks, 256>>>(N, /*use_h=*/1);
    sage_gemm_tc<<<gemm_blocks, 256, SMEM_TOTAL>>>(bl1, out, N, /*layer=*/1);
}